// round 1
// baseline (speedup 1.0000x reference)
#include <cuda_runtime.h>
#include <cuda_bf16.h>

#define N_MAX 100000
#define E_MAX 1600000

// ---------------- device scratch ----------------
__device__ int   g_flag;                 // 1 = edge_index is int64
__device__ int   g_src[E_MAX];
__device__ int   g_dst[E_MAX];
__device__ float g_expsum[N_MAX];
__device__ int   g_count[N_MAX];
__device__ int   g_fill[N_MAX];
__device__ int   g_off[N_MAX + 1];
__device__ int   g_bsum[256];
__device__ int   g_ssrc[E_MAX];
__device__ float g_satt[E_MAX];
__device__ float g_xw[N_MAX * 64];
__device__ float g_h1[N_MAX * 64];

// ---------------- dtype detect ----------------
// If edge_index is int64 (little-endian, values in [0,100000)), every odd
// 32-bit word of the buffer is 0. For int32 the odd words are node indices,
// ~all nonzero. Sample 4096 pairs.
__global__ void detect_kernel(const int* __restrict__ p) {
    __shared__ int cnt;
    if (threadIdx.x == 0) cnt = 0;
    __syncthreads();
    int nz = 0;
    for (int i = threadIdx.x; i < 4096; i += blockDim.x)
        if (p[2 * i + 1] != 0) nz++;
    atomicAdd(&cnt, nz);
    __syncthreads();
    if (threadIdx.x == 0) g_flag = (cnt < 64) ? 1 : 0;
}

// normalize edge_index -> int32 src/dst, and zero the per-node accumulators
__global__ void convert_kernel(const void* __restrict__ eidx, int E, int N) {
    int e = blockIdx.x * blockDim.x + threadIdx.x;
    if (e < N) { g_expsum[e] = 0.f; g_count[e] = 0; g_fill[e] = 0; }
    if (e >= E) return;
    if (g_flag) {
        const long long* p = (const long long*)eidx;
        g_src[e] = (int)p[e];
        g_dst[e] = (int)p[E + e];
    } else {
        const int* p = (const int*)eidx;
        g_src[e] = p[e];
        g_dst[e] = p[E + e];
    }
}

// per-dst sum of exp(attr), and in-degree histogram
__global__ void expsum_kernel(const float* __restrict__ attr, int E) {
    int e = blockIdx.x * blockDim.x + threadIdx.x;
    if (e >= E) return;
    int d = g_dst[e];
    atomicAdd(&g_expsum[d], __expf(attr[e]));
    atomicAdd(&g_count[d], 1);
}

// ---------------- scan (counts -> offsets) ----------------
__global__ void scan1_kernel(int N) {
    __shared__ int s[1024];
    int t = threadIdx.x;
    int i = blockIdx.x * 1024 + t;
    int v = (i < N) ? g_count[i] : 0;
    s[t] = v;
    __syncthreads();
    for (int d2 = 1; d2 < 1024; d2 <<= 1) {
        int w = (t >= d2) ? s[t - d2] : 0;
        __syncthreads();
        s[t] += w;
        __syncthreads();
    }
    if (i < N) g_off[i + 1] = s[t];
    if (t == 1023) g_bsum[blockIdx.x] = s[t];
    if (blockIdx.x == 0 && t == 0) g_off[0] = 0;
}

__global__ void scan2_kernel(int nb) {
    __shared__ int s[256];
    int t = threadIdx.x;
    int v = (t < nb) ? g_bsum[t] : 0;
    s[t] = v;
    __syncthreads();
    for (int d2 = 1; d2 < 256; d2 <<= 1) {
        int w = (t >= d2) ? s[t - d2] : 0;
        __syncthreads();
        s[t] += w;
        __syncthreads();
    }
    if (t < nb) g_bsum[t] = s[t] - v;   // exclusive
}

__global__ void scan3_kernel(int N) {
    int i = blockIdx.x * 1024 + threadIdx.x;
    if (i < N && blockIdx.x > 0) g_off[i + 1] += g_bsum[blockIdx.x];
}

// fill CSR buckets: sorted-by-dst src index and attention weight
__global__ void bucket_kernel(const float* __restrict__ attr, int E) {
    int e = blockIdx.x * blockDim.x + threadIdx.x;
    if (e >= E) return;
    int d = g_dst[e];
    int pos = g_off[d] + atomicAdd(&g_fill[d], 1);
    g_ssrc[pos] = g_src[e];
    g_satt[pos] = __expf(attr[e]) / g_expsum[d];
}

// ---------------- GEMM: XW[n][o] = sum_k X[n][k] * W[o][k] ----------------
template <int CIN>
__global__ void __launch_bounds__(512) gemm_kernel(
    const float* __restrict__ X, const float* __restrict__ W,
    float* __restrict__ XW, int N) {
    __shared__ float Wt[CIN * 64];   // transposed: Wt[k*64+o]
    __shared__ float xs[8 * CIN];
    const int tid = threadIdx.x;
    for (int idx = tid; idx < 64 * CIN; idx += 512) {
        int o = idx / CIN, k = idx % CIN;
        Wt[k * 64 + o] = W[idx];
    }
    __syncthreads();
    int ntiles = (N + 7) / 8;
    for (int tile = blockIdx.x; tile < ntiles; tile += gridDim.x) {
        int base = tile * 8;
        for (int idx = tid; idx < 8 * CIN; idx += 512) {
            int r = idx / CIN, k = idx % CIN;
            int n = base + r;
            xs[idx] = (n < N) ? X[n * CIN + k] : 0.f;
        }
        __syncthreads();
        int r = tid >> 6;
        int o = tid & 63;
        int n = base + r;
        if (n < N) {
            float acc = 0.f;
#pragma unroll
            for (int k = 0; k < CIN; k++)
                acc += xs[r * CIN + k] * Wt[k * 64 + o];
            XW[n * 64 + o] = acc;
        }
        __syncthreads();
    }
}

// ---------------- fused aggregate + self + bias + sigmoid ----------------
// warp per node; lane l owns output cols 2l, 2l+1
__global__ void __launch_bounds__(256) aggregate_kernel(
    const float* __restrict__ XW, const float* __restrict__ b,
    float* __restrict__ H, int N) {
    int warp = (blockIdx.x * blockDim.x + threadIdx.x) >> 5;
    int lane = threadIdx.x & 31;
    if (warp >= N) return;
    int n = warp;
    int i0 = g_off[n], i1 = g_off[n + 1];
    int c = lane * 2;
    float a0 = 0.f, a1 = 0.f;
    for (int i = i0; i < i1; i++) {
        int   s = __ldg(&g_ssrc[i]);
        float a = __ldg(&g_satt[i]);
        float2 v = *(const float2*)(XW + (size_t)s * 64 + c);
        a0 += a * v.x;
        a1 += a * v.y;
    }
    float2 xn = *(const float2*)(XW + (size_t)n * 64 + c);
    float o0 = a0 + xn.x + b[c];
    float o1 = a1 + xn.y + b[c + 1];
    float2 r;
    r.x = 1.f / (1.f + __expf(-o0));
    r.y = 1.f / (1.f + __expf(-o1));
    *(float2*)(H + (size_t)n * 64 + c) = r;
}

// ---------------- launch ----------------
extern "C" void kernel_launch(void* const* d_in, const int* in_sizes, int n_in,
                              void* d_out, int out_size) {
    const float* x    = (const float*)d_in[0];
    const void*  eidx = d_in[1];
    const float* attr = (const float*)d_in[2];
    const float* W1   = (const float*)d_in[3];
    const float* b1   = (const float*)d_in[4];
    const float* W2   = (const float*)d_in[5];
    const float* b2   = (const float*)d_in[6];
    float* out = (float*)d_out;

    int E = in_sizes[2];           // 1,600,000
    int N = out_size / 64;         // 100,000

    void* p;
    cudaGetSymbolAddress(&p, g_xw);  float* xw = (float*)p;
    cudaGetSymbolAddress(&p, g_h1);  float* h1 = (float*)p;

    int eb = (E + 255) / 256;
    int nb = (N + 1023) / 1024;

    // shared preprocessing (att + CSR identical across layers)
    detect_kernel<<<1, 256>>>((const int*)eidx);
    convert_kernel<<<eb, 256>>>(eidx, E, N);
    expsum_kernel<<<eb, 256>>>(attr, E);
    scan1_kernel<<<nb, 1024>>>(N);
    scan2_kernel<<<1, 256>>>(nb);
    scan3_kernel<<<nb, 1024>>>(N);
    bucket_kernel<<<eb, 256>>>(attr, E);

    int agg_blocks = (N + 7) / 8;   // 8 warps per 256-thread block

    // layer 1: x [N,128] -> h1 [N,64]
    gemm_kernel<128><<<592, 512>>>(x, W1, xw, N);
    aggregate_kernel<<<agg_blocks, 256>>>(xw, b1, h1, N);

    // layer 2: h1 [N,64] -> out [N,64]
    gemm_kernel<64><<<592, 512>>>(h1, W2, xw, N);
    aggregate_kernel<<<agg_blocks, 256>>>(xw, b2, out, N);
}

// round 2
// speedup vs baseline: 1.5833x; 1.5833x over previous
#include <cuda_runtime.h>
#include <cuda_bf16.h>

#define N_MAX 100000
#define E_MAX 1600000
#define KC 64

// ---------------- device scratch ----------------
__device__ int    g_flag;                 // 1 = edge_index is int64
__device__ float  g_expsum[N_MAX];
__device__ int    g_count[N_MAX];
__device__ int    g_fill[N_MAX];
__device__ int    g_off[N_MAX + 1];
__device__ int    g_bsum[256];
__device__ float2 g_edge[E_MAX];          // {src_bits, att}
__device__ float  g_xw[N_MAX * 64];
__device__ float  g_h1[N_MAX * 64];

// ---------------- dtype detect ----------------
// int64 little-endian with values < 100000 => every odd 32-bit word is 0.
__global__ void detect_kernel(const int* __restrict__ p) {
    __shared__ int cnt;
    if (threadIdx.x == 0) cnt = 0;
    __syncthreads();
    int nz = 0;
    for (int i = threadIdx.x; i < 4096; i += blockDim.x)
        if (p[2 * i + 1] != 0) nz++;
    atomicAdd(&cnt, nz);
    __syncthreads();
    if (threadIdx.x == 0) g_flag = (cnt < 64) ? 1 : 0;
}

__device__ __forceinline__ int load_idx(const void* eidx, long long i) {
    if (g_flag) return (int)((const long long*)eidx)[i];
    return ((const int*)eidx)[i];
}

// per-dst sum of exp(attr) + in-degree histogram (reads edge_index directly)
__global__ void expsum_kernel(const void* __restrict__ eidx,
                              const float* __restrict__ attr, int E) {
    int e = blockIdx.x * blockDim.x + threadIdx.x;
    if (e >= E) return;
    int d = load_idx(eidx, (long long)E + e);
    atomicAdd(&g_expsum[d], __expf(attr[e]));
    atomicAdd(&g_count[d], 1);
}

// ---------------- scan (counts -> offsets) ----------------
__global__ void scan1_kernel(int N) {
    __shared__ int s[1024];
    int t = threadIdx.x;
    int i = blockIdx.x * 1024 + t;
    int v = (i < N) ? g_count[i] : 0;
    s[t] = v;
    __syncthreads();
    for (int d2 = 1; d2 < 1024; d2 <<= 1) {
        int w = (t >= d2) ? s[t - d2] : 0;
        __syncthreads();
        s[t] += w;
        __syncthreads();
    }
    if (i < N) g_off[i + 1] = s[t];
    if (t == 1023) g_bsum[blockIdx.x] = s[t];
    if (blockIdx.x == 0 && t == 0) g_off[0] = 0;
}

__global__ void scan2_kernel(int nb) {
    __shared__ int s[256];
    int t = threadIdx.x;
    int v = (t < nb) ? g_bsum[t] : 0;
    s[t] = v;
    __syncthreads();
    for (int d2 = 1; d2 < 256; d2 <<= 1) {
        int w = (t >= d2) ? s[t - d2] : 0;
        __syncthreads();
        s[t] += w;
        __syncthreads();
    }
    if (t < nb) g_bsum[t] = s[t] - v;   // exclusive
}

__global__ void scan3_kernel(int N) {
    int i = blockIdx.x * 1024 + threadIdx.x;
    if (i < N && blockIdx.x > 0) g_off[i + 1] += g_bsum[blockIdx.x];
}

// fill CSR buckets: packed {src, att} per edge, sorted by dst
__global__ void bucket_kernel(const void* __restrict__ eidx,
                              const float* __restrict__ attr, int E) {
    int e = blockIdx.x * blockDim.x + threadIdx.x;
    if (e >= E) return;
    int s = load_idx(eidx, e);
    int d = load_idx(eidx, (long long)E + e);
    int pos = g_off[d] + atomicAdd(&g_fill[d], 1);
    g_edge[pos] = make_float2(__int_as_float(s), __expf(attr[e]) / g_expsum[d]);
}

// ---------------- GEMM: XW[n][o] = sum_k X[n][k] * W[o][k] ----------------
// 64-row x 64-col tile, K chunked by KC=64. 512 threads, 4x2 micro-tile.
template <int CIN>
__global__ void __launch_bounds__(512) gemm_kernel(
    const float* __restrict__ X, const float* __restrict__ W,
    float* __restrict__ XW, int N) {
    __shared__ float xs[64][KC];
    __shared__ float wt[KC][64];
    const int tid = threadIdx.x;
    const int cg = tid & 31;        // col pair: cols 2cg, 2cg+1
    const int rg = tid >> 5;        // row group: rows 4rg .. 4rg+3
    const int base = blockIdx.x * 64;

    float acc[4][2] = {};

#pragma unroll
    for (int kc = 0; kc < CIN; kc += KC) {
        // W chunk, transposed into wt[k][o]
        for (int idx = tid; idx < 64 * (KC / 4); idx += 512) {
            int o = idx & 63, k4 = idx >> 6;
            float4 w = *(const float4*)(W + o * CIN + kc + k4 * 4);
            wt[k4 * 4 + 0][o] = w.x;
            wt[k4 * 4 + 1][o] = w.y;
            wt[k4 * 4 + 2][o] = w.z;
            wt[k4 * 4 + 3][o] = w.w;
        }
        // X chunk
        for (int idx = tid; idx < 64 * (KC / 4); idx += 512) {
            int r = idx >> 4, k4 = idx & 15;
            int n = base + r;
            float4 v = (n < N) ? *(const float4*)(X + (size_t)n * CIN + kc + k4 * 4)
                               : make_float4(0.f, 0.f, 0.f, 0.f);
            *(float4*)&xs[r][k4 * 4] = v;
        }
        __syncthreads();

#pragma unroll
        for (int k = 0; k < KC; k += 4) {
            float2 b0 = *(const float2*)&wt[k + 0][cg * 2];
            float2 b1 = *(const float2*)&wt[k + 1][cg * 2];
            float2 b2 = *(const float2*)&wt[k + 2][cg * 2];
            float2 b3 = *(const float2*)&wt[k + 3][cg * 2];
#pragma unroll
            for (int i = 0; i < 4; i++) {
                float4 a = *(const float4*)&xs[rg * 4 + i][k];
                acc[i][0] = fmaf(a.x, b0.x, acc[i][0]);
                acc[i][0] = fmaf(a.y, b1.x, acc[i][0]);
                acc[i][0] = fmaf(a.z, b2.x, acc[i][0]);
                acc[i][0] = fmaf(a.w, b3.x, acc[i][0]);
                acc[i][1] = fmaf(a.x, b0.y, acc[i][1]);
                acc[i][1] = fmaf(a.y, b1.y, acc[i][1]);
                acc[i][1] = fmaf(a.z, b2.y, acc[i][1]);
                acc[i][1] = fmaf(a.w, b3.y, acc[i][1]);
            }
        }
        __syncthreads();
    }

#pragma unroll
    for (int i = 0; i < 4; i++) {
        int n = base + rg * 4 + i;
        if (n < N)
            *(float2*)(XW + (size_t)n * 64 + cg * 2) =
                make_float2(acc[i][0], acc[i][1]);
    }
}

// ---------------- fused aggregate + self + bias + sigmoid ----------------
// warp per node; lane l owns output cols 2l, 2l+1; unroll-4 for MLP
__global__ void __launch_bounds__(256) aggregate_kernel(
    const float* __restrict__ XW, const float* __restrict__ b,
    float* __restrict__ H, int N) {
    int warp = (blockIdx.x * blockDim.x + threadIdx.x) >> 5;
    int lane = threadIdx.x & 31;
    if (warp >= N) return;
    int n = warp;
    int i0 = g_off[n], i1 = g_off[n + 1];
    int c = lane * 2;
    float a0 = 0.f, a1 = 0.f;
    int i = i0;
    for (; i + 4 <= i1; i += 4) {
        float2 e0 = g_edge[i + 0];
        float2 e1 = g_edge[i + 1];
        float2 e2 = g_edge[i + 2];
        float2 e3 = g_edge[i + 3];
        float2 v0 = *(const float2*)(XW + __float_as_int(e0.x) * 64 + c);
        float2 v1 = *(const float2*)(XW + __float_as_int(e1.x) * 64 + c);
        float2 v2 = *(const float2*)(XW + __float_as_int(e2.x) * 64 + c);
        float2 v3 = *(const float2*)(XW + __float_as_int(e3.x) * 64 + c);
        a0 += e0.y * v0.x + e1.y * v1.x + e2.y * v2.x + e3.y * v3.x;
        a1 += e0.y * v0.y + e1.y * v1.y + e2.y * v2.y + e3.y * v3.y;
    }
    for (; i < i1; i++) {
        float2 e0 = g_edge[i];
        float2 v0 = *(const float2*)(XW + __float_as_int(e0.x) * 64 + c);
        a0 += e0.y * v0.x;
        a1 += e0.y * v0.y;
    }
    float2 xn = *(const float2*)(XW + n * 64 + c);
    float o0 = a0 + xn.x + b[c];
    float o1 = a1 + xn.y + b[c + 1];
    float2 r;
    r.x = 1.f / (1.f + __expf(-o0));
    r.y = 1.f / (1.f + __expf(-o1));
    *(float2*)(H + n * 64 + c) = r;
}

// ---------------- launch ----------------
extern "C" void kernel_launch(void* const* d_in, const int* in_sizes, int n_in,
                              void* d_out, int out_size) {
    const float* x    = (const float*)d_in[0];
    const void*  eidx = d_in[1];
    const float* attr = (const float*)d_in[2];
    const float* W1   = (const float*)d_in[3];
    const float* b1   = (const float*)d_in[4];
    const float* W2   = (const float*)d_in[5];
    const float* b2   = (const float*)d_in[6];
    float* out = (float*)d_out;

    int E = in_sizes[2];           // 1,600,000
    int N = out_size / 64;         // 100,000

    void* p;
    cudaGetSymbolAddress(&p, g_xw);     float* xw = (float*)p;
    cudaGetSymbolAddress(&p, g_h1);     float* h1 = (float*)p;
    void *pe, *pc, *pf;
    cudaGetSymbolAddress(&pe, g_expsum);
    cudaGetSymbolAddress(&pc, g_count);
    cudaGetSymbolAddress(&pf, g_fill);

    int eb = (E + 255) / 256;
    int nb = (N + 1023) / 1024;

    // shared preprocessing (att + CSR identical across layers)
    detect_kernel<<<1, 256>>>((const int*)eidx);
    cudaMemsetAsync(pe, 0, N * sizeof(float));
    cudaMemsetAsync(pc, 0, N * sizeof(int));
    cudaMemsetAsync(pf, 0, N * sizeof(int));
    expsum_kernel<<<eb, 256>>>(eidx, attr, E);
    scan1_kernel<<<nb, 1024>>>(N);
    scan2_kernel<<<1, 256>>>(nb);
    scan3_kernel<<<nb, 1024>>>(N);
    bucket_kernel<<<eb, 256>>>(eidx, attr, E);

    int gemm_blocks = (N + 63) / 64;
    int agg_blocks  = (N + 7) / 8;   // 8 warps per 256-thread block

    // layer 1: x [N,128] -> h1 [N,64]
    gemm_kernel<128><<<gemm_blocks, 512>>>(x, W1, xw, N);
    aggregate_kernel<<<agg_blocks, 256>>>(xw, b1, h1, N);

    // layer 2: h1 [N,64] -> out [N,64]
    gemm_kernel<64><<<gemm_blocks, 512>>>(h1, W2, xw, N);
    aggregate_kernel<<<agg_blocks, 256>>>(xw, b2, out, N);
}

// round 3
// speedup vs baseline: 1.8619x; 1.1760x over previous
#include <cuda_runtime.h>
#include <cuda_bf16.h>

#define N_MAX 100000
#define E_MAX 1600000

// ---------------- device scratch ----------------
__device__ int    g_flag;                 // 1 = edge_index is int64
__device__ float  g_expsum[N_MAX];
__device__ int    g_count[N_MAX];
__device__ int    g_fill[N_MAX];
__device__ int    g_off[N_MAX + 1];
__device__ int    g_bsum[256];
__device__ float2 g_edge[E_MAX];          // {src_bits, exp(attr)}
__device__ float  g_xw[N_MAX * 64];
__device__ float  g_h1[N_MAX * 64];

// ---------------- f32x2 packed fma ----------------
__device__ __forceinline__ void ffma2(unsigned long long& d,
                                      unsigned long long a,
                                      unsigned long long b) {
    asm("fma.rn.f32x2 %0, %1, %2, %0;" : "+l"(d) : "l"(a), "l"(b));
}
__device__ __forceinline__ float f32x2_hsum(unsigned long long v) {
    unsigned int lo, hi;
    asm("mov.b64 {%0, %1}, %2;" : "=r"(lo), "=r"(hi) : "l"(v));
    return __uint_as_float(lo) + __uint_as_float(hi);
}

// ---------------- dtype detect ----------------
// int64 little-endian with values < 100000 => every odd 32-bit word is 0.
__global__ void detect_kernel(const int* __restrict__ p) {
    __shared__ int cnt;
    if (threadIdx.x == 0) cnt = 0;
    __syncthreads();
    int nz = 0;
    for (int i = threadIdx.x; i < 4096; i += blockDim.x)
        if (p[2 * i + 1] != 0) nz++;
    atomicAdd(&cnt, nz);
    __syncthreads();
    if (threadIdx.x == 0) g_flag = (cnt < 64) ? 1 : 0;
}

__device__ __forceinline__ int load_idx(const void* eidx, long long i) {
    if (g_flag) return (int)((const long long*)eidx)[i];
    return ((const int*)eidx)[i];
}

// in-degree histogram only (no expsum dependency in the chain)
__global__ void hist_kernel(const void* __restrict__ eidx, int E) {
    int e = blockIdx.x * blockDim.x + threadIdx.x;
    if (e >= E) return;
    int d = load_idx(eidx, (long long)E + e);
    atomicAdd(&g_count[d], 1);
}

// ---------------- scan (counts -> offsets) ----------------
__global__ void scan1_kernel(int N) {
    __shared__ int s[1024];
    int t = threadIdx.x;
    int i = blockIdx.x * 1024 + t;
    int v = (i < N) ? g_count[i] : 0;
    s[t] = v;
    __syncthreads();
    for (int d2 = 1; d2 < 1024; d2 <<= 1) {
        int w = (t >= d2) ? s[t - d2] : 0;
        __syncthreads();
        s[t] += w;
        __syncthreads();
    }
    if (i < N) g_off[i + 1] = s[t];
    if (t == 1023) g_bsum[blockIdx.x] = s[t];
    if (blockIdx.x == 0 && t == 0) g_off[0] = 0;
}

__global__ void scan2_kernel(int nb) {
    __shared__ int s[256];
    int t = threadIdx.x;
    int v = (t < nb) ? g_bsum[t] : 0;
    s[t] = v;
    __syncthreads();
    for (int d2 = 1; d2 < 256; d2 <<= 1) {
        int w = (t >= d2) ? s[t - d2] : 0;
        __syncthreads();
        s[t] += w;
        __syncthreads();
    }
    if (t < nb) g_bsum[t] = s[t] - v;   // exclusive
}

__global__ void scan3_kernel(int N) {
    int i = blockIdx.x * 1024 + threadIdx.x;
    if (i < N && blockIdx.x > 0) g_off[i + 1] += g_bsum[blockIdx.x];
}

// fill CSR buckets: packed {src, exp(attr)}, and accumulate expsum here
__global__ void bucket_kernel(const void* __restrict__ eidx,
                              const float* __restrict__ attr, int E) {
    int e = blockIdx.x * blockDim.x + threadIdx.x;
    if (e >= E) return;
    int s = load_idx(eidx, e);
    int d = load_idx(eidx, (long long)E + e);
    float ex = __expf(attr[e]);
    int pos = g_off[d] + atomicAdd(&g_fill[d], 1);
    g_edge[pos] = make_float2(__int_as_float(s), ex);
    atomicAdd(&g_expsum[d], ex);
}

// ---------------- GEMM: XW[n][o] = sum_k X[n][k] * W[o][k] ----------------
// 128-row x 64-col tile, KC=64 k-chunks, 512 threads.
// f32x2 FMAs packed along K-pairs: acc holds (even-k, odd-k) partial sums.
// Thread (rg = tid>>4, cg = tid&15): rows 4rg..4rg+3, cols cg+16j (j=0..3).
template <int CIN>
__global__ void __launch_bounds__(512, 2) gemm_kernel(
    const float* __restrict__ X, const float* __restrict__ W,
    float* __restrict__ XW, int N) {
    __shared__ float xs[128][64];                  // [row][k] 32KB
    __shared__ unsigned long long wt2[32][64];     // [k-pair][out] 16KB
    const int tid = threadIdx.x;
    const int cg = tid & 15;
    const int rg = tid >> 4;
    const int base = blockIdx.x * 128;

    unsigned long long acc[4][4] = {};

    for (int kc = 0; kc < CIN; kc += 64) {
        // W chunk: wt2[k2][o] = pair W[o][kc+2k2 .. +1]
        for (int idx = tid; idx < 64 * 16; idx += 512) {
            int o = idx & 63, k4 = idx >> 6;
            float4 w = *(const float4*)(W + o * CIN + kc + k4 * 4);
            unsigned long long p0, p1;
            asm("mov.b64 %0, {%1, %2};" : "=l"(p0) : "f"(w.x), "f"(w.y));
            asm("mov.b64 %0, {%1, %2};" : "=l"(p1) : "f"(w.z), "f"(w.w));
            wt2[2 * k4 + 0][o] = p0;
            wt2[2 * k4 + 1][o] = p1;
        }
        // X chunk (coalesced, row-major)
        for (int idx = tid; idx < 128 * 16; idx += 512) {
            int r = idx >> 4, k4 = idx & 15;
            int n = base + r;
            float4 v = (n < N) ? *(const float4*)(X + (size_t)n * CIN + kc + k4 * 4)
                               : make_float4(0.f, 0.f, 0.f, 0.f);
            *(float4*)&xs[r][k4 * 4] = v;
        }
        __syncthreads();

#pragma unroll
        for (int k4 = 0; k4 < 16; k4++) {
            ulonglong2 b[4];
#pragma unroll
            for (int j = 0; j < 4; j++) {
                b[j].x = wt2[2 * k4 + 0][cg + 16 * j];
                b[j].y = wt2[2 * k4 + 1][cg + 16 * j];
            }
#pragma unroll
            for (int i = 0; i < 4; i++) {
                ulonglong2 a = *(const ulonglong2*)&xs[rg * 4 + i][k4 * 4];
#pragma unroll
                for (int j = 0; j < 4; j++) {
                    ffma2(acc[i][j], a.x, b[j].x);
                    ffma2(acc[i][j], a.y, b[j].y);
                }
            }
        }
        __syncthreads();
    }

#pragma unroll
    for (int i = 0; i < 4; i++) {
        int n = base + rg * 4 + i;
        if (n < N) {
#pragma unroll
            for (int j = 0; j < 4; j++)
                XW[(size_t)n * 64 + cg + 16 * j] = f32x2_hsum(acc[i][j]);
        }
    }
}

// ---------------- fused aggregate + softmax-div + self + bias + sigmoid ----
// warp per node; lane l owns output cols 2l, 2l+1; unroll-4 for MLP
__global__ void __launch_bounds__(256) aggregate_kernel(
    const float* __restrict__ XW, const float* __restrict__ b,
    float* __restrict__ H, int N) {
    int warp = (blockIdx.x * blockDim.x + threadIdx.x) >> 5;
    int lane = threadIdx.x & 31;
    if (warp >= N) return;
    int n = warp;
    int i0 = g_off[n], i1 = g_off[n + 1];
    int c = lane * 2;
    float a0 = 0.f, a1 = 0.f;
    int i = i0;
    for (; i + 4 <= i1; i += 4) {
        float2 e0 = g_edge[i + 0];
        float2 e1 = g_edge[i + 1];
        float2 e2 = g_edge[i + 2];
        float2 e3 = g_edge[i + 3];
        float2 v0 = *(const float2*)(XW + __float_as_int(e0.x) * 64 + c);
        float2 v1 = *(const float2*)(XW + __float_as_int(e1.x) * 64 + c);
        float2 v2 = *(const float2*)(XW + __float_as_int(e2.x) * 64 + c);
        float2 v3 = *(const float2*)(XW + __float_as_int(e3.x) * 64 + c);
        a0 += e0.y * v0.x + e1.y * v1.x + e2.y * v2.x + e3.y * v3.x;
        a1 += e0.y * v0.y + e1.y * v1.y + e2.y * v2.y + e3.y * v3.y;
    }
    for (; i < i1; i++) {
        float2 e0 = g_edge[i];
        float2 v0 = *(const float2*)(XW + __float_as_int(e0.x) * 64 + c);
        a0 += e0.y * v0.x;
        a1 += e0.y * v0.y;
    }
    float inv = (i1 > i0) ? 1.f / g_expsum[n] : 0.f;
    float2 xn = *(const float2*)(XW + n * 64 + c);
    float o0 = a0 * inv + xn.x + b[c];
    float o1 = a1 * inv + xn.y + b[c + 1];
    float2 r;
    r.x = 1.f / (1.f + __expf(-o0));
    r.y = 1.f / (1.f + __expf(-o1));
    *(float2*)(H + n * 64 + c) = r;
}

// ---------------- launch ----------------
extern "C" void kernel_launch(void* const* d_in, const int* in_sizes, int n_in,
                              void* d_out, int out_size) {
    const float* x    = (const float*)d_in[0];
    const void*  eidx = d_in[1];
    const float* attr = (const float*)d_in[2];
    const float* W1   = (const float*)d_in[3];
    const float* b1   = (const float*)d_in[4];
    const float* W2   = (const float*)d_in[5];
    const float* b2   = (const float*)d_in[6];
    float* out = (float*)d_out;

    int E = in_sizes[2];           // 1,600,000
    int N = out_size / 64;         // 100,000

    void* p;
    cudaGetSymbolAddress(&p, g_xw);     float* xw = (float*)p;
    cudaGetSymbolAddress(&p, g_h1);     float* h1 = (float*)p;
    void *pe, *pc, *pf;
    cudaGetSymbolAddress(&pe, g_expsum);
    cudaGetSymbolAddress(&pc, g_count);
    cudaGetSymbolAddress(&pf, g_fill);

    int eb = (E + 255) / 256;
    int nb = (N + 1023) / 1024;

    // fork: preprocessing (edge-only) on side stream, gemm1 on main stream
    cudaStream_t s1;
    cudaStreamCreate(&s1);
    cudaEvent_t evFork, evPre;
    cudaEventCreateWithFlags(&evFork, cudaEventDisableTiming);
    cudaEventCreateWithFlags(&evPre, cudaEventDisableTiming);

    cudaEventRecord(evFork, 0);
    cudaStreamWaitEvent(s1, evFork, 0);

    // s1: CSR + attention preprocessing (identical across layers)
    cudaMemsetAsync(pe, 0, N * sizeof(float), s1);
    cudaMemsetAsync(pc, 0, N * sizeof(int), s1);
    cudaMemsetAsync(pf, 0, N * sizeof(int), s1);
    detect_kernel<<<1, 256, 0, s1>>>((const int*)eidx);
    hist_kernel<<<eb, 256, 0, s1>>>(eidx, E);
    scan1_kernel<<<nb, 1024, 0, s1>>>(N);
    scan2_kernel<<<1, 256, 0, s1>>>(nb);
    scan3_kernel<<<nb, 1024, 0, s1>>>(N);
    bucket_kernel<<<eb, 256, 0, s1>>>(eidx, attr, E);
    cudaEventRecord(evPre, s1);

    int gemm_blocks = (N + 127) / 128;
    int agg_blocks  = (N + 7) / 8;   // 8 warps per 256-thread block

    // main stream: layer-1 GEMM overlaps preprocessing
    gemm_kernel<128><<<gemm_blocks, 512>>>(x, W1, xw, N);

    // join, then the serial tail
    cudaStreamWaitEvent(0, evPre, 0);
    aggregate_kernel<<<agg_blocks, 256>>>(xw, b1, h1, N);
    gemm_kernel<64><<<gemm_blocks, 512>>>(h1, W2, xw, N);
    aggregate_kernel<<<agg_blocks, 256>>>(xw, b2, out, N);
}